// round 1
// baseline (speedup 1.0000x reference)
#include <cuda_runtime.h>
#include <math.h>

#define D_MODEL 1024
#define NH      16
#define DK      64
#define BATCH   2
#define SEQ     1024
#define BHT     (BATCH*NH)          // 32
#define MTOT    (BATCH*SEQ)         // 2048

// Scratch (device globals; no allocation allowed)
__device__ float g_Q[BHT*SEQ*DK];   // [b*NH+h][s][d], pre-scaled by 1/sqrt(dk)
__device__ float g_K[BHT*SEQ*DK];
__device__ float g_V[BHT*SEQ*DK];
__device__ float g_O[MTOT*D_MODEL]; // [b*S+s][h*64+d]

// ---------------------------------------------------------------------------
// NT SGEMM: C[m,n] = sum_k A[m,k]*W[n,k] + bias[n]
// mode 0: A = x (2048x1024), N = 3072 (Wq|Wk|Wv), epilogue scatters to g_Q/K/V
// mode 1: A = g_O (2048x1024), N = 1024 (Wo), epilogue -> Cout (+bo)
// 128x128 block tile, BK=16, 8x8 per thread, 256 threads.
// ---------------------------------------------------------------------------
__global__ __launch_bounds__(256, 2)
void sgemm_nt_kernel(const float* __restrict__ Ain,
                     const float* __restrict__ W0, const float* __restrict__ W1,
                     const float* __restrict__ W2,
                     const float* __restrict__ bias0, const float* __restrict__ bias1,
                     const float* __restrict__ bias2,
                     float* __restrict__ Cout, int mode)
{
    const int K = D_MODEL;
    __shared__ float As[16][132];
    __shared__ float Bs[16][132];

    const int tid = threadIdx.x;
    const int tx = tid & 15;
    const int ty = tid >> 4;
    const int m0 = blockIdx.y * 128;
    const int n0 = blockIdx.x * 128;
    const int which = n0 >> 10;          // 0/1/2 (constant per CTA: 128 | 1024)
    const int n0m = n0 & 1023;

    const float* A = (mode == 0) ? Ain : g_O;
    const float* Wm = (which == 0) ? W0 : (which == 1) ? W1 : W2;
    const float* biasm = (which == 0) ? bias0 : (which == 1) ? bias1 : bias2;

    const int lr = tid >> 2;             // 0..63
    const int lk = (tid & 3) << 2;       // 0,4,8,12

    float acc[8][8];
#pragma unroll
    for (int i = 0; i < 8; i++)
#pragma unroll
        for (int j = 0; j < 8; j++) acc[i][j] = 0.f;

    const float* Aptr0 = A + (size_t)(m0 + lr) * K + lk;
    const float* Aptr1 = A + (size_t)(m0 + lr + 64) * K + lk;
    const float* Bptr0 = Wm + (size_t)(n0m + lr) * K + lk;
    const float* Bptr1 = Wm + (size_t)(n0m + lr + 64) * K + lk;

    for (int k0 = 0; k0 < K; k0 += 16) {
        float4 a0 = *(const float4*)(Aptr0 + k0);
        float4 a1 = *(const float4*)(Aptr1 + k0);
        float4 b0 = *(const float4*)(Bptr0 + k0);
        float4 b1 = *(const float4*)(Bptr1 + k0);
        __syncthreads();
        As[lk + 0][lr] = a0.x; As[lk + 1][lr] = a0.y;
        As[lk + 2][lr] = a0.z; As[lk + 3][lr] = a0.w;
        As[lk + 0][lr + 64] = a1.x; As[lk + 1][lr + 64] = a1.y;
        As[lk + 2][lr + 64] = a1.z; As[lk + 3][lr + 64] = a1.w;
        Bs[lk + 0][lr] = b0.x; Bs[lk + 1][lr] = b0.y;
        Bs[lk + 2][lr] = b0.z; Bs[lk + 3][lr] = b0.w;
        Bs[lk + 0][lr + 64] = b1.x; Bs[lk + 1][lr + 64] = b1.y;
        Bs[lk + 2][lr + 64] = b1.z; Bs[lk + 3][lr + 64] = b1.w;
        __syncthreads();
#pragma unroll
        for (int kk = 0; kk < 16; kk++) {
            float a[8], b[8];
            *(float4*)&a[0] = *(const float4*)&As[kk][ty * 8];
            *(float4*)&a[4] = *(const float4*)&As[kk][ty * 8 + 4];
            *(float4*)&b[0] = *(const float4*)&Bs[kk][tx * 8];
            *(float4*)&b[4] = *(const float4*)&Bs[kk][tx * 8 + 4];
#pragma unroll
            for (int i = 0; i < 8; i++)
#pragma unroll
                for (int j = 0; j < 8; j++)
                    acc[i][j] = fmaf(a[i], b[j], acc[i][j]);
        }
    }

    if (mode == 0) {
        float* dst = (which == 0) ? g_Q : (which == 1) ? g_K : g_V;
        const float scale = (which == 0) ? 0.125f : 1.0f;   // 1/sqrt(64)
#pragma unroll
        for (int i = 0; i < 8; i++) {
            int m = m0 + ty * 8 + i;
            int b = m >> 10, s = m & 1023;
#pragma unroll
            for (int j = 0; j < 8; j++) {
                int n1 = n0m + tx * 8 + j;
                int h = n1 >> 6, d = n1 & 63;
                float v = (acc[i][j] + biasm[n1]) * scale;
                dst[((size_t)(b * NH + h) * SEQ + s) * DK + d] = v;
            }
        }
    } else {
#pragma unroll
        for (int i = 0; i < 8; i++) {
            int m = m0 + ty * 8 + i;
#pragma unroll
            for (int j = 0; j < 8; j++) {
                int n = n0 + tx * 8 + j;
                Cout[(size_t)m * D_MODEL + n] = acc[i][j] + biasm[n];
            }
        }
    }
}

// ---------------------------------------------------------------------------
// Fused attention with relative position bias (online softmax).
// scores[i,j] = Qs[i]·K[j] + Qs[i]·Er[S-1+i-j]    (Q pre-scaled by 1/sqrt(dk))
// CTA = one (b,h) and 64 query rows. Loops over 16 key tiles of 64.
// Threads 16x16, each owns a 4x4 score block and 4x4 of the O accumulator.
// ---------------------------------------------------------------------------
#define ATTN_SMEM_FLOATS (4*64*65 + 64*129)
__global__ __launch_bounds__(256, 2)
void attn_kernel(const float* __restrict__ Er)
{
    extern __shared__ float sm[];
    float* Qs = sm;               // [d][i]  stride 65
    float* Ks = Qs + 64 * 65;     // [d][j]  stride 65
    float* Vs = Ks + 64 * 65;     // [j][d]  stride 65
    float* Ps = Vs + 64 * 65;     // [i][j]  stride 65
    float* Es = Ps + 64 * 65;     // [d][r]  stride 129, r in [0,127)

    const int tid = threadIdx.x;
    const int tx = tid & 15;
    const int ty = tid >> 4;
    const int bh = blockIdx.y;
    const int i0 = blockIdx.x * 64;

    const float* Qh = g_Q + (size_t)bh * SEQ * DK;
    const float* Kh = g_K + (size_t)bh * SEQ * DK;
    const float* Vh = g_V + (size_t)bh * SEQ * DK;

    // Load Q tile transposed (d-major)
    for (int idx = tid; idx < 64 * 64; idx += 256) {
        int i = idx >> 6, d = idx & 63;
        Qs[d * 65 + i] = Qh[(size_t)(i0 + i) * DK + d];
    }

    float accO[4][4];
    float rowmax[4], rowsum[4];
#pragma unroll
    for (int ci = 0; ci < 4; ci++) {
        rowmax[ci] = -1e30f; rowsum[ci] = 0.f;
#pragma unroll
        for (int cd = 0; cd < 4; cd++) accO[ci][cd] = 0.f;
    }

    const int ebase = 4 * (ty - tx) + 60;   // in [0,120]

    for (int j0 = 0; j0 < SEQ; j0 += 64) {
        __syncthreads();   // previous tile's PV done before overwrite
        for (int idx = tid; idx < 64 * 64; idx += 256) {
            int jj = idx >> 6, d = idx & 63;
            float kv = Kh[(size_t)(j0 + jj) * DK + d];
            float vv = Vh[(size_t)(j0 + jj) * DK + d];
            Ks[d * 65 + jj] = kv;
            Vs[jj * 65 + d] = vv;
        }
        int rbase = (SEQ - 1) + i0 - j0 - 63;   // always in [0, 2S-2-126]
        for (int idx = tid; idx < 127 * 64; idx += 256) {
            int r = idx >> 6, d = idx & 63;
            Es[d * 129 + r] = Er[(size_t)(rbase + r) * DK + d];
        }
        __syncthreads();

        // ---- scores: AC + BD ----
        float s[4][4];
#pragma unroll
        for (int ci = 0; ci < 4; ci++)
#pragma unroll
            for (int cj = 0; cj < 4; cj++) s[ci][cj] = 0.f;

#pragma unroll 4
        for (int d = 0; d < 64; d++) {
            float q[4], k[4], e[7];
            const float* qrow = Qs + d * 65 + 4 * ty;
            const float* krow = Ks + d * 65 + 4 * tx;
            const float* erow = Es + d * 129 + ebase;
#pragma unroll
            for (int c = 0; c < 4; c++) { q[c] = qrow[c]; k[c] = krow[c]; }
#pragma unroll
            for (int m = 0; m < 7; m++) e[m] = erow[m];
#pragma unroll
            for (int ci = 0; ci < 4; ci++)
#pragma unroll
                for (int cj = 0; cj < 4; cj++)
                    s[ci][cj] = fmaf(q[ci], k[cj] + e[ci - cj + 3], s[ci][cj]);
        }

        // ---- online softmax update ----
        float alpha[4];
#pragma unroll
        for (int ci = 0; ci < 4; ci++) {
            float tm = fmaxf(fmaxf(s[ci][0], s[ci][1]), fmaxf(s[ci][2], s[ci][3]));
#pragma unroll
            for (int o = 8; o >= 1; o >>= 1)
                tm = fmaxf(tm, __shfl_xor_sync(0xffffffffu, tm, o));
            float nm = fmaxf(rowmax[ci], tm);
            alpha[ci] = __expf(rowmax[ci] - nm);
            rowmax[ci] = nm;
            float ls = 0.f;
#pragma unroll
            for (int cj = 0; cj < 4; cj++) {
                float p = __expf(s[ci][cj] - nm);
                s[ci][cj] = p;
                ls += p;
            }
#pragma unroll
            for (int o = 8; o >= 1; o >>= 1)
                ls += __shfl_xor_sync(0xffffffffu, ls, o);
            rowsum[ci] = rowsum[ci] * alpha[ci] + ls;
#pragma unroll
            for (int cd = 0; cd < 4; cd++) accO[ci][cd] *= alpha[ci];
        }

        // stash p tile
#pragma unroll
        for (int ci = 0; ci < 4; ci++)
#pragma unroll
            for (int cj = 0; cj < 4; cj++)
                Ps[(4 * ty + ci) * 65 + 4 * tx + cj] = s[ci][cj];
        __syncthreads();

        // ---- PV accumulate ----
#pragma unroll 4
        for (int j = 0; j < 64; j++) {
            float v[4];
            const float* vrow = Vs + j * 65 + 4 * tx;
#pragma unroll
            for (int cd = 0; cd < 4; cd++) v[cd] = vrow[cd];
#pragma unroll
            for (int ci = 0; ci < 4; ci++) {
                float p = Ps[(4 * ty + ci) * 65 + j];
#pragma unroll
                for (int cd = 0; cd < 4; cd++)
                    accO[ci][cd] = fmaf(p, v[cd], accO[ci][cd]);
            }
        }
    }

    // write O: layout [b*S+s][h*64+d]
    const int b = bh >> 4, h = bh & 15;
#pragma unroll
    for (int ci = 0; ci < 4; ci++) {
        float inv = 1.0f / rowsum[ci];
        int i = i0 + 4 * ty + ci;
#pragma unroll
        for (int cd = 0; cd < 4; cd++) {
            g_O[(size_t)(b * SEQ + i) * D_MODEL + h * DK + 4 * tx + cd] =
                accO[ci][cd] * inv;
        }
    }
}

// ---------------------------------------------------------------------------
extern "C" void kernel_launch(void* const* d_in, const int* in_sizes, int n_in,
                              void* d_out, int out_size)
{
    const float* x  = (const float*)d_in[0];
    const float* Wq = (const float*)d_in[1];
    const float* bq = (const float*)d_in[2];
    const float* Wk = (const float*)d_in[3];
    const float* bk = (const float*)d_in[4];
    const float* Wv = (const float*)d_in[5];
    const float* bv = (const float*)d_in[6];
    const float* Wo = (const float*)d_in[7];
    const float* bo = (const float*)d_in[8];
    const float* Er = (const float*)d_in[9];
    float* out = (float*)d_out;

    const int attn_smem = ATTN_SMEM_FLOATS * (int)sizeof(float);  // 99584 B
    cudaFuncSetAttribute(attn_kernel,
                         cudaFuncAttributeMaxDynamicSharedMemorySize, attn_smem);

    // 1) Fused QKV projection: N = 3072
    {
        dim3 grid(3072 / 128, MTOT / 128);   // 24 x 16
        sgemm_nt_kernel<<<grid, 256>>>(x, Wq, Wk, Wv, bq, bk, bv, nullptr, 0);
    }
    // 2) Attention
    {
        dim3 grid(SEQ / 64, BHT);            // 16 x 32
        attn_kernel<<<grid, 256, attn_smem>>>(Er);
    }
    // 3) Output projection
    {
        dim3 grid(D_MODEL / 128, MTOT / 128);  // 8 x 16
        sgemm_nt_kernel<<<grid, 256>>>(x, Wo, Wo, Wo, bo, bo, bo, out, 1);
    }
}

// round 3
// speedup vs baseline: 1.2714x; 1.2714x over previous
#include <cuda_runtime.h>
#include <cuda_bf16.h>
#include <math.h>
#include <stdint.h>

#define D_MODEL 1024
#define NH      16
#define DK      64
#define BATCH   2
#define SEQ     1024
#define BHT     (BATCH*NH)          // 32
#define MTOT    (BATCH*SEQ)         // 2048

// ---------------- scratch (device globals; no allocation allowed) ----------
__device__ float g_Q[BHT*SEQ*DK];   // head-major, pre-scaled by 1/sqrt(dk)
__device__ float g_K[BHT*SEQ*DK];
__device__ float g_V[BHT*SEQ*DK];
__device__ float g_O[MTOT*D_MODEL]; // [b*S+s][h*64+d]

__device__ __nv_bfloat16 g_xh[MTOT*D_MODEL];
__device__ __nv_bfloat16 g_xl[MTOT*D_MODEL];
__device__ __nv_bfloat16 g_wh[4*D_MODEL*D_MODEL];  // Wq|Wk|Wv|Wo stacked rows
__device__ __nv_bfloat16 g_wl[4*D_MODEL*D_MODEL];
__device__ __nv_bfloat16 g_oh[MTOT*D_MODEL];
__device__ __nv_bfloat16 g_ol[MTOT*D_MODEL];

// ---------------- helpers ---------------------------------------------------
__device__ __forceinline__ uint32_t smem_u32(const void* p) {
    uint32_t a;
    asm("{ .reg .u64 t; cvta.to.shared.u64 t, %1; cvt.u32.u64 %0, t; }"
        : "=r"(a) : "l"(p));
    return a;
}

#define LDMATRIX_X4(r0, r1, r2, r3, addr) \
    asm volatile("ldmatrix.sync.aligned.m8n8.x4.shared.b16 {%0,%1,%2,%3}, [%4];" \
                 : "=r"(r0), "=r"(r1), "=r"(r2), "=r"(r3) : "r"(addr))

#define MMA_BF16(c, a, b) \
    asm volatile("mma.sync.aligned.m16n8k16.row.col.f32.bf16.bf16.f32 " \
                 "{%0,%1,%2,%3}, {%4,%5,%6,%7}, {%8,%9}, {%0,%1,%2,%3};" \
                 : "+f"((c)[0]), "+f"((c)[1]), "+f"((c)[2]), "+f"((c)[3]) \
                 : "r"((a)[0]), "r"((a)[1]), "r"((a)[2]), "r"((a)[3]), \
                   "r"((b)[0]), "r"((b)[1]))

// ---------------------------------------------------------------------------
// fp32 -> bf16 hi/lo split conversion
// ---------------------------------------------------------------------------
__global__ void convert_xw_kernel(const float* __restrict__ x,
                                  const float* __restrict__ Wq, const float* __restrict__ Wk,
                                  const float* __restrict__ Wv, const float* __restrict__ Wo)
{
    const int NX = MTOT * D_MODEL / 4;
    const int NW = D_MODEL * D_MODEL / 4;
    int g = blockIdx.x * blockDim.x + threadIdx.x;
    if (g >= NX + 4 * NW) return;
    const float* src;
    __nv_bfloat16 *dh, *dl;
    if (g < NX) { src = x + g * 4; dh = g_xh + g * 4; dl = g_xl + g * 4; }
    else {
        int wi = g - NX;
        int which = wi / NW;
        int off = wi - which * NW;
        const float* W = (which == 0) ? Wq : (which == 1) ? Wk : (which == 2) ? Wv : Wo;
        src = W + off * 4;
        dh = g_wh + (size_t)which * NW * 4 + off * 4;
        dl = g_wl + (size_t)which * NW * 4 + off * 4;
    }
    float4 v = *(const float4*)src;
    __nv_bfloat16 h0 = __float2bfloat16_rn(v.x), h1 = __float2bfloat16_rn(v.y);
    __nv_bfloat16 h2 = __float2bfloat16_rn(v.z), h3 = __float2bfloat16_rn(v.w);
    __nv_bfloat16 hv[4] = {h0, h1, h2, h3};
    __nv_bfloat16 lv[4] = {
        __float2bfloat16_rn(v.x - __bfloat162float(h0)),
        __float2bfloat16_rn(v.y - __bfloat162float(h1)),
        __float2bfloat16_rn(v.z - __bfloat162float(h2)),
        __float2bfloat16_rn(v.w - __bfloat162float(h3))};
    *(uint2*)dh = *(uint2*)hv;
    *(uint2*)dl = *(uint2*)lv;
}

__global__ void convert_o_kernel()
{
    int g = blockIdx.x * blockDim.x + threadIdx.x;
    if (g >= MTOT * D_MODEL / 4) return;
    float4 v = *(const float4*)(g_O + g * 4);
    __nv_bfloat16 h0 = __float2bfloat16_rn(v.x), h1 = __float2bfloat16_rn(v.y);
    __nv_bfloat16 h2 = __float2bfloat16_rn(v.z), h3 = __float2bfloat16_rn(v.w);
    __nv_bfloat16 hv[4] = {h0, h1, h2, h3};
    __nv_bfloat16 lv[4] = {
        __float2bfloat16_rn(v.x - __bfloat162float(h0)),
        __float2bfloat16_rn(v.y - __bfloat162float(h1)),
        __float2bfloat16_rn(v.z - __bfloat162float(h2)),
        __float2bfloat16_rn(v.w - __bfloat162float(h3))};
    *(uint2*)(g_oh + g * 4) = *(uint2*)hv;
    *(uint2*)(g_ol + g * 4) = *(uint2*)lv;
}

// ---------------------------------------------------------------------------
// Split-bf16 mma.sync GEMM: C[m,n] = sum_k A[m,k]*B[n,k]
//   D = Ah*Bh + Ah*Bl + Al*Bh  (fp32 reg accumulate)
// 128x128 CTA tile, 8 warps (2x4), warp tile 64x32, BK=32, double buffered.
// Smem rows padded to 40 halves (conflict-free ldmatrix/LDS).
// mode 0: epilogue scatters (acc+bias)*scale to g_Q/g_K/g_V (which = n0>>10)
// mode 1: epilogue -> Cout + bias
// ---------------------------------------------------------------------------
#define HSTR 40
#define MAT_HALVES (128*HSTR)                 // 5120 halves per matrix
#define BUF_HALVES (4*MAT_HALVES)             // Ah,Al,Bh,Bl
#define GEMM_DYN_SMEM (2*BUF_HALVES*2)        // bytes: 81920

__global__ __launch_bounds__(256, 1)
void gemm_bf16_kernel(const __nv_bfloat16* __restrict__ Ah, const __nv_bfloat16* __restrict__ Al,
                      const __nv_bfloat16* __restrict__ Bh, const __nv_bfloat16* __restrict__ Bl,
                      const float* __restrict__ bias0, const float* __restrict__ bias1,
                      const float* __restrict__ bias2,
                      float* __restrict__ Cout, int mode)
{
    extern __shared__ __nv_bfloat16 sm[];

    const int tid  = threadIdx.x;
    const int wid  = tid >> 5;
    const int lane = tid & 31;
    const int warp_m = wid >> 2;      // 0..1
    const int warp_n = wid & 3;       // 0..3
    const int m0 = blockIdx.y * 128;
    const int n0 = blockIdx.x * 128;  // absolute (stacked-W row space)
    const int which = n0 >> 10;
    const int n0m = n0 & 1023;
    const float* biasm = (which == 0) ? bias0 : (which == 1) ? bias1 : bias2;

    float acc[4][4][4];
#pragma unroll
    for (int f = 0; f < 4; f++)
#pragma unroll
        for (int g = 0; g < 4; g++)
#pragma unroll
            for (int e = 0; e < 4; e++) acc[f][g][e] = 0.f;

    const int lrow = tid >> 2;          // 0..63
    const int lk   = (tid & 3) * 8;     // 0,8,16,24

    // ---- prologue: load chunk 0 into buffer 0 ----
    {
        __nv_bfloat16* buf = sm;
#pragma unroll
        for (int i = 0; i < 2; i++) {
            int row = lrow + i * 64;
            *(uint4*)&buf[0 * MAT_HALVES + row * HSTR + lk] =
                *(const uint4*)(Ah + (size_t)(m0 + row) * 1024 + lk);
            *(uint4*)&buf[1 * MAT_HALVES + row * HSTR + lk] =
                *(const uint4*)(Al + (size_t)(m0 + row) * 1024 + lk);
            *(uint4*)&buf[2 * MAT_HALVES + row * HSTR + lk] =
                *(const uint4*)(Bh + (size_t)(n0 + row) * 1024 + lk);
            *(uint4*)&buf[3 * MAT_HALVES + row * HSTR + lk] =
                *(const uint4*)(Bl + (size_t)(n0 + row) * 1024 + lk);
        }
    }
    __syncthreads();

    // ldmatrix lane addressing for A frags
    const int a_r   = lane & 15;            // row within 16
    const int a_kof = (lane >> 4) * 8;      // 0 or 8 halves

    for (int c = 0; c < 32; c++) {
        const int cur = c & 1;
        __nv_bfloat16* cb = sm + cur * BUF_HALVES;

        // prefetch next chunk into other buffer
        if (c < 31) {
            __nv_bfloat16* nb = sm + (1 - cur) * BUF_HALVES;
            int kg = (c + 1) * 32 + lk;
#pragma unroll
            for (int i = 0; i < 2; i++) {
                int row = lrow + i * 64;
                *(uint4*)&nb[0 * MAT_HALVES + row * HSTR + lk] =
                    *(const uint4*)(Ah + (size_t)(m0 + row) * 1024 + kg);
                *(uint4*)&nb[1 * MAT_HALVES + row * HSTR + lk] =
                    *(const uint4*)(Al + (size_t)(m0 + row) * 1024 + kg);
                *(uint4*)&nb[2 * MAT_HALVES + row * HSTR + lk] =
                    *(const uint4*)(Bh + (size_t)(n0 + row) * 1024 + kg);
                *(uint4*)&nb[3 * MAT_HALVES + row * HSTR + lk] =
                    *(const uint4*)(Bl + (size_t)(n0 + row) * 1024 + kg);
            }
        }

        // ---- compute on current buffer: 2 k16 steps ----
#pragma unroll
        for (int ks = 0; ks < 2; ks++) {
            uint32_t aH[4][4], aL[4][4], bH[4][2], bL[4][2];
#pragma unroll
            for (int f = 0; f < 4; f++) {
                int row = warp_m * 64 + f * 16 + a_r;
                uint32_t addrH = smem_u32(&cb[0 * MAT_HALVES + row * HSTR + ks * 16 + a_kof]);
                LDMATRIX_X4(aH[f][0], aH[f][1], aH[f][2], aH[f][3], addrH);
                uint32_t addrL = smem_u32(&cb[1 * MAT_HALVES + row * HSTR + ks * 16 + a_kof]);
                LDMATRIX_X4(aL[f][0], aL[f][1], aL[f][2], aL[f][3], addrL);
            }
#pragma unroll
            for (int g = 0; g < 4; g++) {
                int n = warp_n * 32 + g * 8 + (lane >> 2);
                int off = n * HSTR + ks * 16 + (lane & 3) * 2;
                bH[g][0] = *(const uint32_t*)&cb[2 * MAT_HALVES + off];
                bH[g][1] = *(const uint32_t*)&cb[2 * MAT_HALVES + off + 8];
                bL[g][0] = *(const uint32_t*)&cb[3 * MAT_HALVES + off];
                bL[g][1] = *(const uint32_t*)&cb[3 * MAT_HALVES + off + 8];
            }
#pragma unroll
            for (int f = 0; f < 4; f++)
#pragma unroll
                for (int g = 0; g < 4; g++) {
                    MMA_BF16(acc[f][g], aH[f], bH[g]);
                    MMA_BF16(acc[f][g], aH[f], bL[g]);
                    MMA_BF16(acc[f][g], aL[f], bH[g]);
                }
        }
        __syncthreads();
    }

    // ---- epilogue ----
    if (mode == 0) {
        float* dst = (which == 0) ? g_Q : (which == 1) ? g_K : g_V;
        const float scale = (which == 0) ? 0.125f : 1.0f;   // 1/sqrt(64)
#pragma unroll
        for (int f = 0; f < 4; f++) {
            int mrow0 = m0 + warp_m * 64 + f * 16 + (lane >> 2);
#pragma unroll
            for (int g = 0; g < 4; g++) {
                int ncol = n0m + warp_n * 32 + g * 8 + (lane & 3) * 2;
#pragma unroll
                for (int e = 0; e < 4; e++) {
                    int m = mrow0 + (e >> 1) * 8;
                    int nm = ncol + (e & 1);
                    int b = m >> 10, s = m & 1023;
                    int h = nm >> 6, d = nm & 63;
                    float val = (acc[f][g][e] + biasm[nm]) * scale;
                    dst[((size_t)(b * NH + h) * SEQ + s) * DK + d] = val;
                }
            }
        }
    } else {
#pragma unroll
        for (int f = 0; f < 4; f++) {
            int mrow0 = m0 + warp_m * 64 + f * 16 + (lane >> 2);
#pragma unroll
            for (int g = 0; g < 4; g++) {
                int ncol = n0 + warp_n * 32 + g * 8 + (lane & 3) * 2;
#pragma unroll
                for (int e = 0; e < 4; e++) {
                    int m = mrow0 + (e >> 1) * 8;
                    int n = ncol + (e & 1);
                    Cout[(size_t)m * D_MODEL + n] = acc[f][g][e] + biasm[n];
                }
            }
        }
    }
}

// ---------------------------------------------------------------------------
// Fused attention with relative position bias (online softmax). Unchanged.
// ---------------------------------------------------------------------------
#define ATTN_SMEM_FLOATS (4*64*65 + 64*129)
__global__ __launch_bounds__(256, 2)
void attn_kernel(const float* __restrict__ Er)
{
    extern __shared__ float smf[];
    float* Qs = smf;              // [d][i]  stride 65
    float* Ks = Qs + 64 * 65;     // [d][j]
    float* Vs = Ks + 64 * 65;     // [j][d]
    float* Ps = Vs + 64 * 65;     // [i][j]
    float* Es = Ps + 64 * 65;     // [d][r]  stride 129

    const int tid = threadIdx.x;
    const int tx = tid & 15;
    const int ty = tid >> 4;
    const int bh = blockIdx.y;
    const int i0 = blockIdx.x * 64;

    const float* Qh = g_Q + (size_t)bh * SEQ * DK;
    const float* Kh = g_K + (size_t)bh * SEQ * DK;
    const float* Vh = g_V + (size_t)bh * SEQ * DK;

    for (int idx = tid; idx < 64 * 64; idx += 256) {
        int i = idx >> 6, d = idx & 63;
        Qs[d * 65 + i] = Qh[(size_t)(i0 + i) * DK + d];
    }

    float accO[4][4];
    float rowmax[4], rowsum[4];
#pragma unroll
    for (int ci = 0; ci < 4; ci++) {
        rowmax[ci] = -1e30f; rowsum[ci] = 0.f;
#pragma unroll
        for (int cd = 0; cd < 4; cd++) accO[ci][cd] = 0.f;
    }

    const int ebase = 4 * (ty - tx) + 60;

    for (int j0 = 0; j0 < SEQ; j0 += 64) {
        __syncthreads();
        for (int idx = tid; idx < 64 * 64; idx += 256) {
            int jj = idx >> 6, d = idx & 63;
            Ks[d * 65 + jj] = Kh[(size_t)(j0 + jj) * DK + d];
            Vs[jj * 65 + d] = Vh[(size_t)(j0 + jj) * DK + d];
        }
        int rbase = (SEQ - 1) + i0 - j0 - 63;
        for (int idx = tid; idx < 127 * 64; idx += 256) {
            int r = idx >> 6, d = idx & 63;
            Es[d * 129 + r] = Er[(size_t)(rbase + r) * DK + d];
        }
        __syncthreads();

        float s[4][4];
#pragma unroll
        for (int ci = 0; ci < 4; ci++)
#pragma unroll
            for (int cj = 0; cj < 4; cj++) s[ci][cj] = 0.f;

#pragma unroll 4
        for (int d = 0; d < 64; d++) {
            float q[4], k[4], e[7];
            const float* qrow = Qs + d * 65 + 4 * ty;
            const float* krow = Ks + d * 65 + 4 * tx;
            const float* erow = Es + d * 129 + ebase;
#pragma unroll
            for (int c = 0; c < 4; c++) { q[c] = qrow[c]; k[c] = krow[c]; }
#pragma unroll
            for (int m = 0; m < 7; m++) e[m] = erow[m];
#pragma unroll
            for (int ci = 0; ci < 4; ci++)
#pragma unroll
                for (int cj = 0; cj < 4; cj++)
                    s[ci][cj] = fmaf(q[ci], k[cj] + e[ci - cj + 3], s[ci][cj]);
        }

        float alpha[4];
#pragma unroll
        for (int ci = 0; ci < 4; ci++) {
            float tm = fmaxf(fmaxf(s[ci][0], s[ci][1]), fmaxf(s[ci][2], s[ci][3]));
#pragma unroll
            for (int o = 8; o >= 1; o >>= 1)
                tm = fmaxf(tm, __shfl_xor_sync(0xffffffffu, tm, o));
            float nm = fmaxf(rowmax[ci], tm);
            alpha[ci] = __expf(rowmax[ci] - nm);
            rowmax[ci] = nm;
            float ls = 0.f;
#pragma unroll
            for (int cj = 0; cj < 4; cj++) {
                float p = __expf(s[ci][cj] - nm);
                s[ci][cj] = p;
                ls += p;
            }
#pragma unroll
            for (int o = 8; o >= 1; o >>= 1)
                ls += __shfl_xor_sync(0xffffffffu, ls, o);
            rowsum[ci] = rowsum[ci] * alpha[ci] + ls;
#pragma unroll
            for (int cd = 0; cd < 4; cd++) accO[ci][cd] *= alpha[ci];
        }

#pragma unroll
        for (int ci = 0; ci < 4; ci++)
#pragma unroll
            for (int cj = 0; cj < 4; cj++)
                Ps[(4 * ty + ci) * 65 + 4 * tx + cj] = s[ci][cj];
        __syncthreads();

#pragma unroll 4
        for (int j = 0; j < 64; j++) {
            float v[4];
            const float* vrow = Vs + j * 65 + 4 * tx;
#pragma unroll
            for (int cd = 0; cd < 4; cd++) v[cd] = vrow[cd];
#pragma unroll
            for (int ci = 0; ci < 4; ci++) {
                float p = Ps[(4 * ty + ci) * 65 + j];
#pragma unroll
                for (int cd = 0; cd < 4; cd++)
                    accO[ci][cd] = fmaf(p, v[cd], accO[ci][cd]);
            }
        }
    }

    const int b = bh >> 4, h = bh & 15;
#pragma unroll
    for (int ci = 0; ci < 4; ci++) {
        float inv = 1.0f / rowsum[ci];
        int i = i0 + 4 * ty + ci;
#pragma unroll
        for (int cd = 0; cd < 4; cd++) {
            g_O[(size_t)(b * SEQ + i) * D_MODEL + h * DK + 4 * tx + cd] =
                accO[ci][cd] * inv;
        }
    }
}

// ---------------------------------------------------------------------------
extern "C" void kernel_launch(void* const* d_in, const int* in_sizes, int n_in,
                              void* d_out, int out_size)
{
    const float* x  = (const float*)d_in[0];
    const float* Wq = (const float*)d_in[1];
    const float* bq = (const float*)d_in[2];
    const float* Wk = (const float*)d_in[3];
    const float* bk = (const float*)d_in[4];
    const float* Wv = (const float*)d_in[5];
    const float* bv = (const float*)d_in[6];
    const float* Wo = (const float*)d_in[7];
    const float* bo = (const float*)d_in[8];
    const float* Er = (const float*)d_in[9];
    float* out = (float*)d_out;

    cudaFuncSetAttribute(gemm_bf16_kernel,
                         cudaFuncAttributeMaxDynamicSharedMemorySize, GEMM_DYN_SMEM);
    const int attn_smem = ATTN_SMEM_FLOATS * (int)sizeof(float);
    cudaFuncSetAttribute(attn_kernel,
                         cudaFuncAttributeMaxDynamicSharedMemorySize, attn_smem);

    __nv_bfloat16 *xh, *xl, *wh, *wl, *oh, *ol;
    cudaGetSymbolAddress((void**)&xh, g_xh);
    cudaGetSymbolAddress((void**)&xl, g_xl);
    cudaGetSymbolAddress((void**)&wh, g_wh);
    cudaGetSymbolAddress((void**)&wl, g_wl);
    cudaGetSymbolAddress((void**)&oh, g_oh);
    cudaGetSymbolAddress((void**)&ol, g_ol);

    // 0) split x and all weights into bf16 hi/lo
    {
        int total = (MTOT * D_MODEL + 4 * D_MODEL * D_MODEL) / 4;
        convert_xw_kernel<<<(total + 255) / 256, 256>>>(x, Wq, Wk, Wv, Wo);
    }
    // 1) fused QKV projection (N = 3072) -> g_Q/g_K/g_V
    {
        dim3 grid(3072 / 128, MTOT / 128);   // 24 x 16
        gemm_bf16_kernel<<<grid, 256, GEMM_DYN_SMEM>>>(
            xh, xl, wh, wl, bq, bk, bv, nullptr, 0);
    }
    // 2) attention -> g_O
    {
        dim3 grid(SEQ / 64, BHT);            // 16 x 32
        attn_kernel<<<grid, 256, attn_smem>>>(Er);
    }
    // 3) split g_O
    {
        int total = MTOT * D_MODEL / 4;
        convert_o_kernel<<<(total + 255) / 256, 256>>>();
    }
    // 4) output projection -> out
    {
        dim3 grid(D_MODEL / 128, MTOT / 128);  // 8 x 16
        gemm_bf16_kernel<<<grid, 256, GEMM_DYN_SMEM>>>(
            oh, ol, wh + (size_t)3 * D_MODEL * D_MODEL, wl + (size_t)3 * D_MODEL * D_MODEL,
            bo, bo, bo, out, 1);
    }
}

// round 4
// speedup vs baseline: 2.0617x; 1.6216x over previous
#include <cuda_runtime.h>
#include <cuda_bf16.h>
#include <math.h>
#include <stdint.h>

#define D_MODEL 1024
#define NH      16
#define DK      64
#define BATCH   2
#define SEQ     1024
#define BHT     (BATCH*NH)          // 32
#define MTOT    (BATCH*SEQ)         // 2048
#define ELEN    (2*SEQ-1)           // 2047

// ---------------- scratch (device globals; no allocation allowed) ----------
__device__ __nv_bfloat16 g_xh[MTOT*D_MODEL];
__device__ __nv_bfloat16 g_xl[MTOT*D_MODEL];
__device__ __nv_bfloat16 g_wh[4*D_MODEL*D_MODEL];  // Wq|Wk|Wv|Wo stacked rows
__device__ __nv_bfloat16 g_wl[4*D_MODEL*D_MODEL];
__device__ __nv_bfloat16 g_oh[MTOT*D_MODEL];
__device__ __nv_bfloat16 g_ol[MTOT*D_MODEL];

__device__ __nv_bfloat16 g_Qh[BHT*SEQ*DK];   // [bh][s][d], pre-scaled 1/8
__device__ __nv_bfloat16 g_Ql[BHT*SEQ*DK];
__device__ __nv_bfloat16 g_Kh[BHT*SEQ*DK];   // [bh][s][d]
__device__ __nv_bfloat16 g_Kl[BHT*SEQ*DK];
__device__ __nv_bfloat16 g_Vth[BHT*DK*SEQ];  // [bh][d][s]  (transposed)
__device__ __nv_bfloat16 g_Vtl[BHT*DK*SEQ];
__device__ __nv_bfloat16 g_Eh[ELEN*DK];
__device__ __nv_bfloat16 g_El[ELEN*DK];

// ---------------- helpers ---------------------------------------------------
__device__ __forceinline__ uint32_t smem_u32(const void* p) {
    uint32_t a;
    asm("{ .reg .u64 t; cvta.to.shared.u64 t, %1; cvt.u32.u64 %0, t; }"
        : "=r"(a) : "l"(p));
    return a;
}

#define LDMATRIX_X4(r0, r1, r2, r3, addr) \
    asm volatile("ldmatrix.sync.aligned.m8n8.x4.shared.b16 {%0,%1,%2,%3}, [%4];" \
                 : "=r"(r0), "=r"(r1), "=r"(r2), "=r"(r3) : "r"(addr))

#define MMA_BF16(c, a, b) \
    asm volatile("mma.sync.aligned.m16n8k16.row.col.f32.bf16.bf16.f32 " \
                 "{%0,%1,%2,%3}, {%4,%5,%6,%7}, {%8,%9}, {%0,%1,%2,%3};" \
                 : "+f"((c)[0]), "+f"((c)[1]), "+f"((c)[2]), "+f"((c)[3]) \
                 : "r"((a)[0]), "r"((a)[1]), "r"((a)[2]), "r"((a)[3]), \
                   "r"((b)[0]), "r"((b)[1]))

__device__ __forceinline__ uint32_t pack_bf2(float lo, float hi) {
    __nv_bfloat162 t = __floats2bfloat162_rn(lo, hi);
    return *(uint32_t*)&t;
}
__device__ __forceinline__ void split_bf(float v, __nv_bfloat16& h, __nv_bfloat16& l) {
    h = __float2bfloat16_rn(v);
    l = __float2bfloat16_rn(v - __bfloat162float(h));
}

// ---------------------------------------------------------------------------
// fp32 -> bf16 hi/lo split conversion (x, 4 weights, Er)
// ---------------------------------------------------------------------------
__global__ void convert_xw_kernel(const float* __restrict__ x,
                                  const float* __restrict__ Wq, const float* __restrict__ Wk,
                                  const float* __restrict__ Wv, const float* __restrict__ Wo,
                                  const float* __restrict__ Er)
{
    const int NX = MTOT * D_MODEL / 4;
    const int NW = D_MODEL * D_MODEL / 4;
    const int NE = ELEN * DK / 4;
    int g = blockIdx.x * blockDim.x + threadIdx.x;
    if (g >= NX + 4 * NW + NE) return;
    const float* src;
    __nv_bfloat16 *dh, *dl;
    if (g < NX) { src = x + g * 4; dh = g_xh + g * 4; dl = g_xl + g * 4; }
    else if (g < NX + 4 * NW) {
        int wi = g - NX;
        int which = wi / NW;
        int off = wi - which * NW;
        const float* W = (which == 0) ? Wq : (which == 1) ? Wk : (which == 2) ? Wv : Wo;
        src = W + off * 4;
        dh = g_wh + (size_t)which * NW * 4 + off * 4;
        dl = g_wl + (size_t)which * NW * 4 + off * 4;
    } else {
        int ei = g - NX - 4 * NW;
        src = Er + ei * 4; dh = g_Eh + ei * 4; dl = g_El + ei * 4;
    }
    float4 v = *(const float4*)src;
    __nv_bfloat16 hv[4], lv[4];
    split_bf(v.x, hv[0], lv[0]); split_bf(v.y, hv[1], lv[1]);
    split_bf(v.z, hv[2], lv[2]); split_bf(v.w, hv[3], lv[3]);
    *(uint2*)dh = *(uint2*)hv;
    *(uint2*)dl = *(uint2*)lv;
}

// ---------------------------------------------------------------------------
// Split-bf16 mma.sync GEMM: C[m,n] = sum_k A[m,k]*B[n,k]
// mode 0: epilogue -> split-bf16 Q/K (head-major) and V (transposed)
// mode 1: epilogue -> Cout fp32 + bias
// ---------------------------------------------------------------------------
#define HSTR 40
#define MAT_HALVES (128*HSTR)
#define BUF_HALVES (4*MAT_HALVES)
#define GEMM_DYN_SMEM (2*BUF_HALVES*2)        // 81920 B

__global__ __launch_bounds__(256, 1)
void gemm_bf16_kernel(const __nv_bfloat16* __restrict__ Ah, const __nv_bfloat16* __restrict__ Al,
                      const __nv_bfloat16* __restrict__ Bh, const __nv_bfloat16* __restrict__ Bl,
                      const float* __restrict__ bias0, const float* __restrict__ bias1,
                      const float* __restrict__ bias2,
                      float* __restrict__ Cout, int mode)
{
    extern __shared__ __nv_bfloat16 sm[];

    const int tid  = threadIdx.x;
    const int wid  = tid >> 5;
    const int lane = tid & 31;
    const int warp_m = wid >> 2;
    const int warp_n = wid & 3;
    const int m0 = blockIdx.y * 128;
    const int n0 = blockIdx.x * 128;
    const int which = n0 >> 10;
    const int n0m = n0 & 1023;
    const float* biasm = (which == 0) ? bias0 : (which == 1) ? bias1 : bias2;

    float acc[4][4][4];
#pragma unroll
    for (int f = 0; f < 4; f++)
#pragma unroll
        for (int g = 0; g < 4; g++)
#pragma unroll
            for (int e = 0; e < 4; e++) acc[f][g][e] = 0.f;

    const int lrow = tid >> 2;
    const int lk   = (tid & 3) * 8;

    {
        __nv_bfloat16* buf = sm;
#pragma unroll
        for (int i = 0; i < 2; i++) {
            int row = lrow + i * 64;
            *(uint4*)&buf[0 * MAT_HALVES + row * HSTR + lk] =
                *(const uint4*)(Ah + (size_t)(m0 + row) * 1024 + lk);
            *(uint4*)&buf[1 * MAT_HALVES + row * HSTR + lk] =
                *(const uint4*)(Al + (size_t)(m0 + row) * 1024 + lk);
            *(uint4*)&buf[2 * MAT_HALVES + row * HSTR + lk] =
                *(const uint4*)(Bh + (size_t)(n0 + row) * 1024 + lk);
            *(uint4*)&buf[3 * MAT_HALVES + row * HSTR + lk] =
                *(const uint4*)(Bl + (size_t)(n0 + row) * 1024 + lk);
        }
    }
    __syncthreads();

    const int a_r   = lane & 15;
    const int a_kof = (lane >> 4) * 8;

    for (int c = 0; c < 32; c++) {
        const int cur = c & 1;
        __nv_bfloat16* cb = sm + cur * BUF_HALVES;

        if (c < 31) {
            __nv_bfloat16* nb = sm + (1 - cur) * BUF_HALVES;
            int kg = (c + 1) * 32 + lk;
#pragma unroll
            for (int i = 0; i < 2; i++) {
                int row = lrow + i * 64;
                *(uint4*)&nb[0 * MAT_HALVES + row * HSTR + lk] =
                    *(const uint4*)(Ah + (size_t)(m0 + row) * 1024 + kg);
                *(uint4*)&nb[1 * MAT_HALVES + row * HSTR + lk] =
                    *(const uint4*)(Al + (size_t)(m0 + row) * 1024 + kg);
                *(uint4*)&nb[2 * MAT_HALVES + row * HSTR + lk] =
                    *(const uint4*)(Bh + (size_t)(n0 + row) * 1024 + kg);
                *(uint4*)&nb[3 * MAT_HALVES + row * HSTR + lk] =
                    *(const uint4*)(Bl + (size_t)(n0 + row) * 1024 + kg);
            }
        }

#pragma unroll
        for (int ks = 0; ks < 2; ks++) {
            uint32_t aH[4][4], aL[4][4], bH[4][2], bL[4][2];
#pragma unroll
            for (int f = 0; f < 4; f++) {
                int row = warp_m * 64 + f * 16 + a_r;
                uint32_t addrH = smem_u32(&cb[0 * MAT_HALVES + row * HSTR + ks * 16 + a_kof]);
                LDMATRIX_X4(aH[f][0], aH[f][1], aH[f][2], aH[f][3], addrH);
                uint32_t addrL = smem_u32(&cb[1 * MAT_HALVES + row * HSTR + ks * 16 + a_kof]);
                LDMATRIX_X4(aL[f][0], aL[f][1], aL[f][2], aL[f][3], addrL);
            }
#pragma unroll
            for (int g = 0; g < 4; g++) {
                int n = warp_n * 32 + g * 8 + (lane >> 2);
                int off = n * HSTR + ks * 16 + (lane & 3) * 2;
                bH[g][0] = *(const uint32_t*)&cb[2 * MAT_HALVES + off];
                bH[g][1] = *(const uint32_t*)&cb[2 * MAT_HALVES + off + 8];
                bL[g][0] = *(const uint32_t*)&cb[3 * MAT_HALVES + off];
                bL[g][1] = *(const uint32_t*)&cb[3 * MAT_HALVES + off + 8];
            }
#pragma unroll
            for (int f = 0; f < 4; f++)
#pragma unroll
                for (int g = 0; g < 4; g++) {
                    MMA_BF16(acc[f][g], aH[f], bH[g]);
                    MMA_BF16(acc[f][g], aH[f], bL[g]);
                    MMA_BF16(acc[f][g], aL[f], bH[g]);
                }
        }
        __syncthreads();
    }

    if (mode == 0) {
        const float scale = (which == 0) ? 0.125f : 1.0f;
#pragma unroll
        for (int f = 0; f < 4; f++) {
            int mrow0 = m0 + warp_m * 64 + f * 16 + (lane >> 2);
#pragma unroll
            for (int g = 0; g < 4; g++) {
                int ncol = n0m + warp_n * 32 + g * 8 + (lane & 3) * 2;
#pragma unroll
                for (int e = 0; e < 4; e++) {
                    int m = mrow0 + (e >> 1) * 8;
                    int nm = ncol + (e & 1);
                    int b = m >> 10, s = m & 1023;
                    int h = nm >> 6, d = nm & 63;
                    float val = (acc[f][g][e] + biasm[nm]) * scale;
                    __nv_bfloat16 vh, vl;
                    split_bf(val, vh, vl);
                    if (which == 2) {
                        size_t idx = ((size_t)(b * NH + h) * DK + d) * SEQ + s;
                        g_Vth[idx] = vh; g_Vtl[idx] = vl;
                    } else if (which == 0) {
                        size_t idx = ((size_t)(b * NH + h) * SEQ + s) * DK + d;
                        g_Qh[idx] = vh; g_Ql[idx] = vl;
                    } else {
                        size_t idx = ((size_t)(b * NH + h) * SEQ + s) * DK + d;
                        g_Kh[idx] = vh; g_Kl[idx] = vl;
                    }
                }
            }
        }
    } else {
#pragma unroll
        for (int f = 0; f < 4; f++) {
            int mrow0 = m0 + warp_m * 64 + f * 16 + (lane >> 2);
#pragma unroll
            for (int g = 0; g < 4; g++) {
                int ncol = n0 + warp_n * 32 + g * 8 + (lane & 3) * 2;
#pragma unroll
                for (int e = 0; e < 4; e++) {
                    int m = mrow0 + (e >> 1) * 8;
                    int n = ncol + (e & 1);
                    Cout[(size_t)m * D_MODEL + n] = acc[f][g][e] + biasm[n];
                }
            }
        }
    }
}

// ---------------------------------------------------------------------------
// MMA flash-attention with relative position (G-gather for BD).
// CTA: 128 threads (4 warps), one (b,h), 64 query rows. 16 key tiles of 64.
// Per warp: 16 query rows. S tile via AC mma + gather from G = Q*Eband^T mma.
// ---------------------------------------------------------------------------
#define ASTR 72
#define GSTR 132
// smem: K(2) 64x72, Vt(2) 64x72, E(2) 128x72, G 64x132 fp32
#define ATTN_SMEM (4*64*ASTR*2 + 2*128*ASTR*2 + 64*GSTR*4)   // 107520 B

__global__ __launch_bounds__(128)
void attn_mma_kernel()
{
    extern __shared__ char smraw[];
    __nv_bfloat16* sKh = (__nv_bfloat16*)smraw;        // [j][d] pad 72
    __nv_bfloat16* sKl = sKh + 64 * ASTR;
    __nv_bfloat16* sVh = sKl + 64 * ASTR;              // [d][j] pad 72
    __nv_bfloat16* sVl = sVh + 64 * ASTR;
    __nv_bfloat16* sEh = sVl + 64 * ASTR;              // [r][d] pad 72, 127 rows
    __nv_bfloat16* sEl = sEh + 128 * ASTR;
    float* sG = (float*)(sEl + 128 * ASTR);            // [i][r] pad 132
    __nv_bfloat16* sQh = (__nv_bfloat16*)sG;           // staging overlay
    __nv_bfloat16* sQl = sQh + 64 * ASTR;

    const int tid  = threadIdx.x;
    const int lane = tid & 31;
    const int w    = tid >> 5;
    const int bh = blockIdx.y;
    const int i0 = blockIdx.x * 64;
    const int b = bh >> 4, h = bh & 15;

    const __nv_bfloat16* Qhg = g_Qh + (size_t)bh * SEQ * DK;
    const __nv_bfloat16* Qlg = g_Ql + (size_t)bh * SEQ * DK;
    const __nv_bfloat16* Khg = g_Kh + (size_t)bh * SEQ * DK;
    const __nv_bfloat16* Klg = g_Kl + (size_t)bh * SEQ * DK;
    const __nv_bfloat16* Vhg = g_Vth + (size_t)bh * DK * SEQ;
    const __nv_bfloat16* Vlg = g_Vtl + (size_t)bh * DK * SEQ;

    // stage Q, load A-fragments once
    for (int t = tid; t < 512; t += 128) {
        int r = t >> 3, c8 = (t & 7) * 8;
        *(uint4*)&sQh[r * ASTR + c8] = *(const uint4*)(Qhg + (size_t)(i0 + r) * DK + c8);
        *(uint4*)&sQl[r * ASTR + c8] = *(const uint4*)(Qlg + (size_t)(i0 + r) * DK + c8);
    }
    __syncthreads();
    uint32_t qh[4][4], ql[4][4];
#pragma unroll
    for (int ks = 0; ks < 4; ks++) {
        uint32_t aH = smem_u32(&sQh[(w * 16 + (lane & 15)) * ASTR + ks * 16 + (lane >> 4) * 8]);
        LDMATRIX_X4(qh[ks][0], qh[ks][1], qh[ks][2], qh[ks][3], aH);
        uint32_t aL = smem_u32(&sQl[(w * 16 + (lane & 15)) * ASTR + ks * 16 + (lane >> 4) * 8]);
        LDMATRIX_X4(ql[ks][0], ql[ks][1], ql[ks][2], ql[ks][3], aL);
    }

    float accO[8][4];
#pragma unroll
    for (int nf = 0; nf < 8; nf++)
#pragma unroll
        for (int e = 0; e < 4; e++) accO[nf][e] = 0.f;
    float rmax0 = -1e30f, rmax1 = -1e30f, rsum0 = 0.f, rsum1 = 0.f;

    const int r0 = lane >> 2;
    const int c0 = (lane & 3) * 2;

    for (int jt = 0; jt < 16; jt++) {
        const int j0 = jt * 64;
        __syncthreads();   // everyone done with prev K/V/E/G (and Q ldmatrix)
        for (int t = tid; t < 512; t += 128) {
            int r = t >> 3, c8 = (t & 7) * 8;
            *(uint4*)&sKh[r * ASTR + c8] = *(const uint4*)(Khg + (size_t)(j0 + r) * DK + c8);
            *(uint4*)&sKl[r * ASTR + c8] = *(const uint4*)(Klg + (size_t)(j0 + r) * DK + c8);
            *(uint4*)&sVh[r * ASTR + c8] = *(const uint4*)(Vhg + (size_t)r * SEQ + j0 + c8);
            *(uint4*)&sVl[r * ASTR + c8] = *(const uint4*)(Vlg + (size_t)r * SEQ + j0 + c8);
        }
        const int rbase = (SEQ - 1) + i0 - j0 - 63;
        for (int t = tid; t < 1016; t += 128) {
            int r = t >> 3, c8 = (t & 7) * 8;
            *(uint4*)&sEh[r * ASTR + c8] = *(const uint4*)(g_Eh + (size_t)(rbase + r) * DK + c8);
            *(uint4*)&sEl[r * ASTR + c8] = *(const uint4*)(g_El + (size_t)(rbase + r) * DK + c8);
        }
        __syncthreads();

        // ---- G = Q * Eband^T  (16 n-frags of 8) ----
        float gac[16][4];
#pragma unroll
        for (int nf = 0; nf < 16; nf++)
#pragma unroll
            for (int e = 0; e < 4; e++) gac[nf][e] = 0.f;
#pragma unroll
        for (int ks = 0; ks < 4; ks++) {
#pragma unroll
            for (int nf = 0; nf < 16; nf++) {
                uint32_t beh[2], bel[2];
                int off = (nf * 8 + r0) * ASTR + ks * 16 + c0;
                beh[0] = *(const uint32_t*)&sEh[off];
                beh[1] = *(const uint32_t*)&sEh[off + 8];
                bel[0] = *(const uint32_t*)&sEl[off];
                bel[1] = *(const uint32_t*)&sEl[off + 8];
                MMA_BF16(gac[nf], qh[ks], beh);
                MMA_BF16(gac[nf], qh[ks], bel);
                MMA_BF16(gac[nf], ql[ks], beh);
            }
        }
        // store G tile (each warp owns rows w*16..+16)
#pragma unroll
        for (int nf = 0; nf < 16; nf++) {
            *(float2*)&sG[(w * 16 + r0) * GSTR + nf * 8 + c0] =
                make_float2(gac[nf][0], gac[nf][1]);
            *(float2*)&sG[(w * 16 + r0 + 8) * GSTR + nf * 8 + c0] =
                make_float2(gac[nf][2], gac[nf][3]);
        }

        // ---- S = Q * K^T ----
        float s[8][4];
#pragma unroll
        for (int nf = 0; nf < 8; nf++)
#pragma unroll
            for (int e = 0; e < 4; e++) s[nf][e] = 0.f;
#pragma unroll
        for (int ks = 0; ks < 4; ks++) {
#pragma unroll
            for (int nf = 0; nf < 8; nf++) {
                uint32_t bkh[2], bkl[2];
                int off = (nf * 8 + r0) * ASTR + ks * 16 + c0;
                bkh[0] = *(const uint32_t*)&sKh[off];
                bkh[1] = *(const uint32_t*)&sKh[off + 8];
                bkl[0] = *(const uint32_t*)&sKl[off];
                bkl[1] = *(const uint32_t*)&sKl[off + 8];
                MMA_BF16(s[nf], qh[ks], bkh);
                MMA_BF16(s[nf], qh[ks], bkl);
                MMA_BF16(s[nf], ql[ks], bkh);
            }
        }
        __syncwarp();   // G writes visible within warp (rows are warp-private)

        // ---- gather BD from G and add ----
#pragma unroll
        for (int nf = 0; nf < 8; nf++)
#pragma unroll
            for (int e = 0; e < 4; e++) {
                int il = w * 16 + r0 + ((e >> 1) << 3);
                int jl = nf * 8 + c0 + (e & 1);
                s[nf][e] += sG[il * GSTR + (il - jl + 63)];
            }

        // ---- online softmax ----
        float mx0 = -1e30f, mx1 = -1e30f;
#pragma unroll
        for (int nf = 0; nf < 8; nf++) {
            mx0 = fmaxf(mx0, fmaxf(s[nf][0], s[nf][1]));
            mx1 = fmaxf(mx1, fmaxf(s[nf][2], s[nf][3]));
        }
#pragma unroll
        for (int o = 1; o <= 2; o <<= 1) {
            mx0 = fmaxf(mx0, __shfl_xor_sync(0xffffffffu, mx0, o));
            mx1 = fmaxf(mx1, __shfl_xor_sync(0xffffffffu, mx1, o));
        }
        float nm0 = fmaxf(rmax0, mx0), nm1 = fmaxf(rmax1, mx1);
        float al0 = __expf(rmax0 - nm0), al1 = __expf(rmax1 - nm1);
        rmax0 = nm0; rmax1 = nm1;
        float ls0 = 0.f, ls1 = 0.f;
#pragma unroll
        for (int nf = 0; nf < 8; nf++) {
            s[nf][0] = __expf(s[nf][0] - nm0);
            s[nf][1] = __expf(s[nf][1] - nm0);
            s[nf][2] = __expf(s[nf][2] - nm1);
            s[nf][3] = __expf(s[nf][3] - nm1);
            ls0 += s[nf][0] + s[nf][1];
            ls1 += s[nf][2] + s[nf][3];
        }
#pragma unroll
        for (int o = 1; o <= 2; o <<= 1) {
            ls0 += __shfl_xor_sync(0xffffffffu, ls0, o);
            ls1 += __shfl_xor_sync(0xffffffffu, ls1, o);
        }
        rsum0 = rsum0 * al0 + ls0;
        rsum1 = rsum1 * al1 + ls1;
#pragma unroll
        for (int nf = 0; nf < 8; nf++) {
            accO[nf][0] *= al0; accO[nf][1] *= al0;
            accO[nf][2] *= al1; accO[nf][3] *= al1;
        }

        // ---- pack P fragments (hi + residual-lo) ----
        uint32_t ph[4][4], pl[4][4];
#pragma unroll
        for (int ks = 0; ks < 4; ks++) {
            int f0 = 2 * ks, f1 = 2 * ks + 1;
            float rlo[8];
#pragma unroll
            for (int e = 0; e < 4; e++) {
                rlo[e]     = s[f0][e] - __bfloat162float(__float2bfloat16_rn(s[f0][e]));
                rlo[4 + e] = s[f1][e] - __bfloat162float(__float2bfloat16_rn(s[f1][e]));
            }
            ph[ks][0] = pack_bf2(s[f0][0], s[f0][1]);
            ph[ks][1] = pack_bf2(s[f0][2], s[f0][3]);
            ph[ks][2] = pack_bf2(s[f1][0], s[f1][1]);
            ph[ks][3] = pack_bf2(s[f1][2], s[f1][3]);
            pl[ks][0] = pack_bf2(rlo[0], rlo[1]);
            pl[ks][1] = pack_bf2(rlo[2], rlo[3]);
            pl[ks][2] = pack_bf2(rlo[4], rlo[5]);
            pl[ks][3] = pack_bf2(rlo[6], rlo[7]);
        }

        // ---- O += P * V ----
#pragma unroll
        for (int ks = 0; ks < 4; ks++) {
#pragma unroll
            for (int nf = 0; nf < 8; nf++) {
                uint32_t bvh[2], bvl[2];
                int off = (nf * 8 + r0) * ASTR + ks * 16 + c0;
                bvh[0] = *(const uint32_t*)&sVh[off];
                bvh[1] = *(const uint32_t*)&sVh[off + 8];
                bvl[0] = *(const uint32_t*)&sVl[off];
                bvl[1] = *(const uint32_t*)&sVl[off + 8];
                MMA_BF16(accO[nf], ph[ks], bvh);
                MMA_BF16(accO[nf], ph[ks], bvl);
                MMA_BF16(accO[nf], pl[ks], bvh);
            }
        }
    }

    // ---- epilogue: O / rowsum, split to bf16 hi/lo ----
    float inv0 = 1.0f / rsum0, inv1 = 1.0f / rsum1;
#pragma unroll
    for (int nf = 0; nf < 8; nf++)
#pragma unroll
        for (int e = 0; e < 4; e++) {
            int i = i0 + w * 16 + r0 + ((e >> 1) << 3);
            int d = nf * 8 + c0 + (e & 1);
            float v = accO[nf][e] * ((e < 2) ? inv0 : inv1);
            __nv_bfloat16 vh, vl;
            split_bf(v, vh, vl);
            size_t idx = ((size_t)(b * SEQ + i)) * D_MODEL + h * DK + d;
            g_oh[idx] = vh; g_ol[idx] = vl;
        }
}

// ---------------------------------------------------------------------------
extern "C" void kernel_launch(void* const* d_in, const int* in_sizes, int n_in,
                              void* d_out, int out_size)
{
    const float* x  = (const float*)d_in[0];
    const float* Wq = (const float*)d_in[1];
    const float* bq = (const float*)d_in[2];
    const float* Wk = (const float*)d_in[3];
    const float* bk = (const float*)d_in[4];
    const float* Wv = (const float*)d_in[5];
    const float* bv = (const float*)d_in[6];
    const float* Wo = (const float*)d_in[7];
    const float* bo = (const float*)d_in[8];
    const float* Er = (const float*)d_in[9];
    float* out = (float*)d_out;

    cudaFuncSetAttribute(gemm_bf16_kernel,
                         cudaFuncAttributeMaxDynamicSharedMemorySize, GEMM_DYN_SMEM);
    cudaFuncSetAttribute(attn_mma_kernel,
                         cudaFuncAttributeMaxDynamicSharedMemorySize, ATTN_SMEM);

    __nv_bfloat16 *xh, *xl, *wh, *wl, *oh, *ol;
    cudaGetSymbolAddress((void**)&xh, g_xh);
    cudaGetSymbolAddress((void**)&xl, g_xl);
    cudaGetSymbolAddress((void**)&wh, g_wh);
    cudaGetSymbolAddress((void**)&wl, g_wl);
    cudaGetSymbolAddress((void**)&oh, g_oh);
    cudaGetSymbolAddress((void**)&ol, g_ol);

    // 0) split x, weights, Er into bf16 hi/lo
    {
        int total = (MTOT * D_MODEL + 4 * D_MODEL * D_MODEL + ELEN * DK) / 4;
        convert_xw_kernel<<<(total + 255) / 256, 256>>>(x, Wq, Wk, Wv, Wo, Er);
    }
    // 1) fused QKV projection -> split-bf16 Q/K (head-major) + V^T
    {
        dim3 grid(3072 / 128, MTOT / 128);
        gemm_bf16_kernel<<<grid, 256, GEMM_DYN_SMEM>>>(
            xh, xl, wh, wl, bq, bk, bv, nullptr, 0);
    }
    // 2) MMA attention -> split-bf16 O
    {
        dim3 grid(SEQ / 64, BHT);            // 16 x 32
        attn_mma_kernel<<<grid, 128, ATTN_SMEM>>>();
    }
    // 3) output projection -> out
    {
        dim3 grid(D_MODEL / 128, MTOT / 128);
        gemm_bf16_kernel<<<grid, 256, GEMM_DYN_SMEM>>>(
            oh, ol, wh + (size_t)3 * D_MODEL * D_MODEL, wl + (size_t)3 * D_MODEL * D_MODEL,
            bo, bo, bo, out, 1);
    }
}